// round 3
// baseline (speedup 1.0000x reference)
#include <cuda_runtime.h>

typedef unsigned long long u64;
#define DINL __device__ __forceinline__

DINL u64 pack2(float lo, float hi) {
    u64 r;
    asm("mov.b64 %0, {%1, %2};" : "=l"(r) : "r"(__float_as_uint(lo)), "r"(__float_as_uint(hi)));
    return r;
}
DINL void unpack2(u64 v, float& lo, float& hi) {
    unsigned int a, b;
    asm("mov.b64 {%0, %1}, %2;" : "=r"(a), "=r"(b) : "l"(v));
    lo = __uint_as_float(a);
    hi = __uint_as_float(b);
}
DINL u64 fma2(u64 a, u64 b, u64 c) {
    u64 d;
    asm("fma.rn.f32x2 %0, %1, %2, %3;" : "=l"(d) : "l"(a), "l"(b), "l"(c));
    return d;
}
DINL u64 add2(u64 a, u64 b) {
    u64 d;
    asm("add.rn.f32x2 %0, %1, %2;" : "=l"(d) : "l"(a), "l"(b));
    return d;
}

// Shapes: B=2, N=256, N1=N2=128, C=Co=16.
// h[b,n,j,k,o] = relu(base[b,n,o] + U[b,j,o] + V[b,k,o])
//   base = x.(Wa-Wb-Wc) + b1 ;  U = x1.Wb ;  V = x2.Wc
// h2 = relu(h @ W2 + b2); out = concat(max_{j,k} h2[:,:8], mean_{j,k} h2[:,8:])
//
// Block = one (b,n). Warp w owns j in [16w, 16w+16). For g in {0,1}, lane owns
// k-pair {64g+lane, 64g+lane+32}. z accumulators: z[kidx][pp] packed over
// p-pairs as f32x2 (2*8 u64 = 32 regs).

__global__ void __launch_bounds__(256, 2)
ppr3_kernel(const float* __restrict__ x, const float* __restrict__ x1,
            const float* __restrict__ x2, const float* __restrict__ W1,
            const float* __restrict__ b1, const float* __restrict__ W2,
            const float* __restrict__ b2, float* __restrict__ out)
{
    __shared__ __align__(16) u64 sUd[128][16];  // dup'd base+U: {v,v}
    __shared__ __align__(16) u64 sVp[16][64];   // [o][g*32+l] = {V[64g+l], V[64g+l+32]}
    __shared__ __align__(16) u64 sW2p[16][8];   // W2 row o packed over p-pairs
    __shared__ u64   sB2p[8];
    __shared__ float sBase[16];
    __shared__ float sRed[8][16];

    const int bx   = blockIdx.x;     // b*256 + n
    const int b    = bx >> 8;
    const int tid  = threadIdx.x;
    const int lane = tid & 31;
    const int w    = tid >> 5;

    // ---------------- setup ----------------
    if (tid < 128) {
        int o = tid >> 3, pp = tid & 7;
        sW2p[o][pp] = pack2(W2[o * 16 + 2 * pp], W2[o * 16 + 2 * pp + 1]);
    } else if (tid < 136) {
        int pp = tid - 128;
        sB2p[pp] = pack2(b2[2 * pp], b2[2 * pp + 1]);
    } else if (tid < 152) {
        int o = tid - 136;
        float s = b1[o];
        const float* xr = x + bx * 16;
        #pragma unroll
        for (int c = 0; c < 16; c++)
            s += xr[c] * (W1[c * 16 + o] - W1[(16 + c) * 16 + o] - W1[(32 + c) * 16 + o]);
        sBase[o] = s;
    }

    // V pairs: [o][g*32+l] = {V[64g+l][o], V[64g+l+32][o]}  (1024 entries)
    {
        const float* x2b = x2 + b * 2048;
        for (int idx = tid; idx < 1024; idx += 256) {
            int o = idx >> 6, kk = idx & 63;
            int g = kk >> 5, l = kk & 31;
            int klo = 64 * g + l, khi = klo + 32;
            const float* rlo = x2b + klo * 16;
            const float* rhi = x2b + khi * 16;
            float slo = 0.f, shi = 0.f;
            #pragma unroll
            for (int c = 0; c < 16; c++) {
                float wv = W1[(32 + c) * 16 + o];
                slo += rlo[c] * wv;
                shi += rhi[c] * wv;
            }
            sVp[o][kk] = pack2(slo, shi);
        }
    }
    __syncthreads();

    // U with base folded, stored duplicated {v,v}
    {
        const float* x1b = x1 + b * 2048;
        for (int idx = tid; idx < 2048; idx += 256) {
            int j = idx >> 4, o = idx & 15;
            float s = sBase[o];
            const float* xr = x1b + j * 16;
            #pragma unroll
            for (int c = 0; c < 16; c++) s += xr[c] * W1[(16 + c) * 16 + o];
            sUd[j][o] = pack2(s, s);
        }
    }
    __syncthreads();

    // ---------------- main loop ----------------
    u64 b2r[8];
    #pragma unroll
    for (int pp = 0; pp < 8; pp++) b2r[pp] = sB2p[pp];

    float mx[8], sv[8];
    #pragma unroll
    for (int p = 0; p < 8; p++) { mx[p] = 0.f; sv[p] = 0.f; }  // relu(max)=max(0,..)

    #pragma unroll 1
    for (int jj = 0; jj < 16; jj++) {
        const u64* uj = sUd[(w << 4) + jj];

        #pragma unroll 1
        for (int g = 0; g < 2; g++) {
            u64 z0[8], z1[8];
            #pragma unroll
            for (int pp = 0; pp < 8; pp++) { z0[pp] = b2r[pp]; z1[pp] = b2r[pp]; }

            #pragma unroll
            for (int o = 0; o < 16; o++) {
                u64 s = add2(uj[o], sVp[o][(g << 5) + lane]);  // {u+v0, u+v1}
                float a0, a1;
                unpack2(s, a0, a1);
                float t0 = fmaxf(a0, 0.f), t1 = fmaxf(a1, 0.f);
                u64 d0 = pack2(t0, t0), d1 = pack2(t1, t1);

                const ulonglong2* wrow = reinterpret_cast<const ulonglong2*>(sW2p[o]);
                #pragma unroll
                for (int q = 0; q < 4; q++) {
                    ulonglong2 wq = wrow[q];   // LDS.128 broadcast: two p-pairs
                    int pp = 2 * q;
                    z0[pp]     = fma2(d0, wq.x, z0[pp]);
                    z1[pp]     = fma2(d1, wq.x, z1[pp]);
                    z0[pp + 1] = fma2(d0, wq.y, z0[pp + 1]);
                    z1[pp + 1] = fma2(d1, wq.y, z1[pp + 1]);
                }
            }

            // epilogue: pp<4 -> max pool (p 0..7); pp>=4 -> sum of relu (p 8..15)
            #pragma unroll
            for (int pp = 0; pp < 4; pp++) {
                float a, c, e, f;
                unpack2(z0[pp], a, c);
                unpack2(z1[pp], e, f);
                mx[2 * pp]     = fmaxf(mx[2 * pp],     fmaxf(a, e));
                mx[2 * pp + 1] = fmaxf(mx[2 * pp + 1], fmaxf(c, f));
            }
            #pragma unroll
            for (int pp = 4; pp < 8; pp++) {
                float a, c, e, f;
                unpack2(z0[pp], a, c);
                unpack2(z1[pp], e, f);
                sv[2 * (pp - 4)]     += fmaxf(a, 0.f) + fmaxf(e, 0.f);
                sv[2 * (pp - 4) + 1] += fmaxf(c, 0.f) + fmaxf(f, 0.f);
            }
        }
    }

    // ---------------- reductions ----------------
    #pragma unroll
    for (int off = 16; off; off >>= 1) {
        #pragma unroll
        for (int p = 0; p < 8; p++) {
            mx[p] = fmaxf(mx[p], __shfl_xor_sync(0xffffffffu, mx[p], off));
            sv[p] += __shfl_xor_sync(0xffffffffu, sv[p], off);
        }
    }
    if (lane == 0) {
        #pragma unroll
        for (int p = 0; p < 8; p++) {
            sRed[w][p]     = mx[p];
            sRed[w][8 + p] = sv[p];
        }
    }
    __syncthreads();
    if (tid < 16) {
        float r;
        if (tid < 8) {
            r = sRed[0][tid];
            #pragma unroll
            for (int ww = 1; ww < 8; ww++) r = fmaxf(r, sRed[ww][tid]);
        } else {
            r = 0.f;
            #pragma unroll
            for (int ww = 0; ww < 8; ww++) r += sRed[ww][tid];
            r *= (1.0f / 16384.0f);
        }
        out[bx * 16 + tid] = r;
    }
}

extern "C" void kernel_launch(void* const* d_in, const int* in_sizes, int n_in,
                              void* d_out, int out_size)
{
    const float* x  = (const float*)d_in[0];
    const float* x1 = (const float*)d_in[1];
    const float* x2 = (const float*)d_in[2];
    const float* W1 = (const float*)d_in[3];
    const float* b1 = (const float*)d_in[4];
    const float* W2 = (const float*)d_in[5];
    const float* b2 = (const float*)d_in[6];

    const int grid = in_sizes[0] / 16;   // B*N = 512
    ppr3_kernel<<<grid, 256>>>(x, x1, x2, W1, b1, W2, b2, (float*)d_out);
}

// round 5
// speedup vs baseline: 3.4497x; 3.4497x over previous
#include <cuda_runtime.h>

typedef unsigned long long u64;
#define DINL __device__ __forceinline__

DINL u64 pack2(float lo, float hi) {
    u64 r;
    asm("mov.b64 %0, {%1, %2};" : "=l"(r) : "r"(__float_as_uint(lo)), "r"(__float_as_uint(hi)));
    return r;
}
DINL void unpack2(u64 v, float& lo, float& hi) {
    unsigned int a, b;
    asm("mov.b64 {%0, %1}, %2;" : "=r"(a), "=r"(b) : "l"(v));
    lo = __uint_as_float(a);
    hi = __uint_as_float(b);
}
DINL u64 fma2(u64 a, u64 b, u64 c) {
    u64 d;
    asm("fma.rn.f32x2 %0, %1, %2, %3;" : "=l"(d) : "l"(a), "l"(b), "l"(c));
    return d;
}

// Shapes: B=2, N=256, N1=N2=128, C=Co=16.
// h[b,n,j,k,o] = relu(base[b,n,o] + U[b,j,o] + V[b,k,o])
//   base = x.(Wa-Wb-Wc) + b1 ;  U = x1.Wb ;  V = x2.Wc
// h2 = relu(h @ W2 + b2); out = concat(max_{j,k} h2[:,:8], mean_{j,k} h2[:,8:])
//
// Block = one (b,n). Warp w owns j in [16w, 16w+16). For g in {0,1}, lane owns
// k-pair {64g+lane, 64g+lane+32}. z[k][pp]: f32x2 over p-pairs (32 regs).
// o-loop unrolled only 2x to keep ptxas's load-hoisting window (and thus
// register pressure) small — R1/R3 spilled to DRAM from full unroll.

__global__ void __launch_bounds__(256, 2)
ppr3_kernel(const float* __restrict__ x, const float* __restrict__ x1,
            const float* __restrict__ x2, const float* __restrict__ W1,
            const float* __restrict__ b1, const float* __restrict__ W2,
            const float* __restrict__ b2, float* __restrict__ out)
{
    __shared__ __align__(16) float  sU[128][16];   // base + U[j][o]
    __shared__ __align__(16) float2 sVp[16][64];   // [o][g*32+l] = {V[64g+l], V[64g+l+32]}
    __shared__ __align__(16) u64    sW2p[16][8];   // W2 row o packed over p-pairs
    __shared__ u64   sB2p[8];
    __shared__ float sBase[16];
    __shared__ float sRed[8][16];

    const int bx   = blockIdx.x;     // b*256 + n
    const int b    = bx >> 8;
    const int tid  = threadIdx.x;
    const int lane = tid & 31;
    const int w    = tid >> 5;

    // ---------------- setup ----------------
    if (tid < 128) {
        int o = tid >> 3, pp = tid & 7;
        sW2p[o][pp] = pack2(W2[o * 16 + 2 * pp], W2[o * 16 + 2 * pp + 1]);
    } else if (tid < 136) {
        int pp = tid - 128;
        sB2p[pp] = pack2(b2[2 * pp], b2[2 * pp + 1]);
    } else if (tid < 152) {
        int o = tid - 136;
        float s = b1[o];
        const float* xr = x + bx * 16;
        #pragma unroll
        for (int c = 0; c < 16; c++)
            s += xr[c] * (W1[c * 16 + o] - W1[(16 + c) * 16 + o] - W1[(32 + c) * 16 + o]);
        sBase[o] = s;
    }

    // V pairs: [o][g*32+l] = {V[64g+l][o], V[64g+l+32][o]}
    {
        const float* x2b = x2 + b * 2048;
        for (int idx = tid; idx < 1024; idx += 256) {
            int o = idx >> 6, kk = idx & 63;
            int g = kk >> 5, l = kk & 31;
            int klo = 64 * g + l, khi = klo + 32;
            const float* rlo = x2b + klo * 16;
            const float* rhi = x2b + khi * 16;
            float slo = 0.f, shi = 0.f;
            #pragma unroll
            for (int c = 0; c < 16; c++) {
                float wv = W1[(32 + c) * 16 + o];
                slo += rlo[c] * wv;
                shi += rhi[c] * wv;
            }
            sVp[o][kk] = make_float2(slo, shi);
        }
    }
    __syncthreads();

    // U with base folded
    {
        const float* x1b = x1 + b * 2048;
        for (int idx = tid; idx < 2048; idx += 256) {
            int j = idx >> 4, o = idx & 15;
            float s = sBase[o];
            const float* xr = x1b + j * 16;
            #pragma unroll
            for (int c = 0; c < 16; c++) s += xr[c] * W1[(16 + c) * 16 + o];
            sU[j][o] = s;
        }
    }
    __syncthreads();

    // ---------------- main loop ----------------
    float mx[8], sv[8];
    #pragma unroll
    for (int p = 0; p < 8; p++) { mx[p] = 0.f; sv[p] = 0.f; }  // relu(max)=max(0,..)

    #pragma unroll 1
    for (int jj = 0; jj < 16; jj++) {
        // U row into registers (4x LDS.128 broadcast)
        float u[16];
        {
            const float4* ur = reinterpret_cast<const float4*>(sU[(w << 4) + jj]);
            #pragma unroll
            for (int q = 0; q < 4; q++) {
                float4 t = ur[q];
                u[4 * q] = t.x; u[4 * q + 1] = t.y; u[4 * q + 2] = t.z; u[4 * q + 3] = t.w;
            }
        }

        #pragma unroll 1
        for (int g = 0; g < 2; g++) {
            u64 z0[8], z1[8];
            #pragma unroll
            for (int pp = 0; pp < 8; pp++) {
                u64 bb = sB2p[pp];
                z0[pp] = bb; z1[pp] = bb;
            }

            #pragma unroll 2
            for (int o = 0; o < 16; o++) {
                float2 v = sVp[o][(g << 5) + lane];
                float t0 = fmaxf(u[o] + v.x, 0.f);
                float t1 = fmaxf(u[o] + v.y, 0.f);
                u64 d0 = pack2(t0, t0);
                u64 d1 = pack2(t1, t1);

                const ulonglong2* wrow = reinterpret_cast<const ulonglong2*>(sW2p[o]);
                #pragma unroll
                for (int q = 0; q < 4; q++) {
                    ulonglong2 wq = wrow[q];   // LDS.128 broadcast
                    int pp = 2 * q;
                    z0[pp]     = fma2(d0, wq.x, z0[pp]);
                    z1[pp]     = fma2(d1, wq.x, z1[pp]);
                    z0[pp + 1] = fma2(d0, wq.y, z0[pp + 1]);
                    z1[pp + 1] = fma2(d1, wq.y, z1[pp + 1]);
                }
            }

            // epilogue: pp<4 -> max pool (p 0..7); pp>=4 -> sum of relu (p 8..15)
            #pragma unroll
            for (int pp = 0; pp < 4; pp++) {
                float a, c, e, f;
                unpack2(z0[pp], a, c);
                unpack2(z1[pp], e, f);
                mx[2 * pp]     = fmaxf(mx[2 * pp],     fmaxf(a, e));
                mx[2 * pp + 1] = fmaxf(mx[2 * pp + 1], fmaxf(c, f));
            }
            #pragma unroll
            for (int pp = 4; pp < 8; pp++) {
                float a, c, e, f;
                unpack2(z0[pp], a, c);
                unpack2(z1[pp], e, f);
                sv[2 * (pp - 4)]     += fmaxf(a, 0.f) + fmaxf(e, 0.f);
                sv[2 * (pp - 4) + 1] += fmaxf(c, 0.f) + fmaxf(f, 0.f);
            }
        }
    }

    // ---------------- reductions ----------------
    #pragma unroll
    for (int off = 16; off; off >>= 1) {
        #pragma unroll
        for (int p = 0; p < 8; p++) {
            mx[p] = fmaxf(mx[p], __shfl_xor_sync(0xffffffffu, mx[p], off));
            sv[p] += __shfl_xor_sync(0xffffffffu, sv[p], off);
        }
    }
    if (lane == 0) {
        #pragma unroll
        for (int p = 0; p < 8; p++) {
            sRed[w][p]     = mx[p];
            sRed[w][8 + p] = sv[p];
        }
    }
    __syncthreads();
    if (tid < 16) {
        float r;
        if (tid < 8) {
            r = sRed[0][tid];
            #pragma unroll
            for (int ww = 1; ww < 8; ww++) r = fmaxf(r, sRed[ww][tid]);
        } else {
            r = 0.f;
            #pragma unroll
            for (int ww = 0; ww < 8; ww++) r += sRed[ww][tid];
            r *= (1.0f / 16384.0f);
        }
        out[bx * 16 + tid] = r;
    }
}

extern "C" void kernel_launch(void* const* d_in, const int* in_sizes, int n_in,
                              void* d_out, int out_size)
{
    const float* x  = (const float*)d_in[0];
    const float* x1 = (const float*)d_in[1];
    const float* x2 = (const float*)d_in[2];
    const float* W1 = (const float*)d_in[3];
    const float* b1 = (const float*)d_in[4];
    const float* W2 = (const float*)d_in[5];
    const float* b2 = (const float*)d_in[6];

    const int grid = in_sizes[0] / 16;   // B*N = 512
    ppr3_kernel<<<grid, 256>>>(x, x1, x2, W1, b1, W2, b2, (float*)d_out);
}